// round 2
// baseline (speedup 1.0000x reference)
#include <cuda_runtime.h>
#include <math.h>
#include <float.h>

#define BB 32
#define NPG0 4096
#define DEGV 16
#define OUTD 23
#define N0 131072
#define E_TOT (N0*DEGV)
#define KK1 2458
#define NN1 (BB*KK1)
#define KK2 1475
#define NN2 (BB*KK2)
#define KK3 885
#define NN3 (BB*KK3)
#define DIVC 1.0e-4f

// ------------------ scratch (device globals) -------------------------------
__device__ float g_h24[N0*24];      // features; later reused for pooled h
__device__ float g_hdA[N0*16];      // hd ping
__device__ float g_hdB[N0*16];      // hd pong
__device__ float g_hP [N0*16];      // h written for pooling
__device__ float g_dinv[N0];
__device__ int   g_esrc[E_TOT];
__device__ int   g_edst[E_TOT];
__device__ int   g_esrc2[E_TOT/2];
__device__ int   g_edst2[E_TOT/2];
__device__ int   g_col [E_TOT];
__device__ int   g_coff[N0];
__device__ int   g_cur [N0];
__device__ int   g_deg [N0];
__device__ int   g_np  [N0];
__device__ int   g_bsums[128];
__device__ int   g_ecnt;

// ------------------ feature build ------------------------------------------
__global__ void feat_kernel(const int* __restrict__ x, const float4* __restrict__ eg4,
                            const float4* __restrict__ ea4, float4* __restrict__ h24) {
    int n = blockIdx.x*blockDim.x + threadIdx.x;
    if (n >= N0) return;
    int g = x[n*4+0];
    int a = x[n*4+3];
    float4* o = h24 + (size_t)n*6;
    #pragma unroll
    for (int i = 0; i < 4; i++) o[i] = eg4[(size_t)g*4 + i];
    // replicate jnp.concatenate([sin, cos], axis=0).reshape(-1,2) exactly
    float xe[2], ye[2];
    #pragma unroll
    for (int c = 0; c < 2; c++) {
        int j = 2*n + c;
        if (j < N0) {
            xe[c] = sinf((float)x[j*4+1]*DIVC);
            ye[c] = sinf((float)x[j*4+2]*DIVC);
        } else {
            int jj = j - N0;
            xe[c] = cosf((float)x[jj*4+1]*DIVC);
            ye[c] = cosf((float)x[jj*4+2]*DIVC);
        }
    }
    o[4] = make_float4(xe[0], xe[1], ye[0], ye[1]);
    o[5] = ea4[a];
}

// ------------------ CSR build ----------------------------------------------
__global__ void hist0_kernel(const int* __restrict__ edst, int* __restrict__ deg) {
    for (int e = blockIdx.x*blockDim.x + threadIdx.x; e < E_TOT; e += gridDim.x*blockDim.x)
        atomicAdd(&deg[edst[e]], 1);
}

__global__ void scan_block_kernel(const int* __restrict__ in, int* __restrict__ out,
                                  int* __restrict__ bsums, int N) {
    __shared__ int sh[1024];
    int tid = threadIdx.x;
    int gid = blockIdx.x*1024 + tid;
    int v = (gid < N) ? in[gid] : 0;
    sh[tid] = v;
    __syncthreads();
    for (int off = 1; off < 1024; off <<= 1) {
        int t = (tid >= off) ? sh[tid-off] : 0;
        __syncthreads();
        sh[tid] += t;
        __syncthreads();
    }
    if (gid < N) out[gid] = sh[tid] - v;
    if (tid == 1023) bsums[blockIdx.x] = sh[1023];
}

__global__ void scan_sums_kernel(int* __restrict__ bsums) {
    __shared__ int sh[128];
    int tid = threadIdx.x;
    int v = bsums[tid];
    sh[tid] = v;
    __syncthreads();
    for (int off = 1; off < 128; off <<= 1) {
        int t = (tid >= off) ? sh[tid-off] : 0;
        __syncthreads();
        sh[tid] += t;
        __syncthreads();
    }
    bsums[tid] = sh[tid] - v;
}

__global__ void finalize_kernel(int* __restrict__ coff, int* __restrict__ cur,
                                float* __restrict__ dinv, const int* __restrict__ deg,
                                const int* __restrict__ bsums, int N) {
    int n = blockIdx.x*1024 + threadIdx.x;
    if (n >= N) return;
    int off = coff[n] + bsums[blockIdx.x];
    coff[n] = off;
    cur[n]  = off;
    dinv[n] = rsqrtf((float)deg[n] + 1.0f);
}

// scatter: ecnt==nullptr -> use Efixed
__global__ void scatter_kernel(const int* __restrict__ es, const int* __restrict__ ed,
                               int* __restrict__ cur, int* __restrict__ col,
                               int Efixed, const int* __restrict__ ecnt) {
    int E = ecnt ? *ecnt : Efixed;
    for (int e = blockIdx.x*blockDim.x + threadIdx.x; e < E; e += gridDim.x*blockDim.x) {
        int d = ed[e];
        int p = atomicAdd(&cur[d], 1);
        col[p] = es[e];
    }
}

// remap + compact + degree-hist fused (warp-aggregated counter)
__global__ void remap_compact(const int* __restrict__ es, const int* __restrict__ ed,
                              int Efixed, const int* __restrict__ ecnt_in,
                              const int* __restrict__ np,
                              int* __restrict__ nes, int* __restrict__ ned,
                              int* __restrict__ deg, int* __restrict__ ecnt_out) {
    int E = ecnt_in ? *ecnt_in : Efixed;
    int lane = threadIdx.x & 31;
    int idx = blockIdx.x*blockDim.x + threadIdx.x;
    int stride = gridDim.x*blockDim.x;
    for (int e = idx; e - lane < E; e += stride) {
        bool valid = false;
        int ns = 0, nd = 0;
        if (e < E) {
            ns = np[es[e]];
            nd = np[ed[e]];
            valid = (ns >= 0) && (nd >= 0);
        }
        unsigned m = __ballot_sync(0xffffffffu, valid);
        int cnt = __popc(m);
        int base = 0;
        if (lane == 0 && cnt) base = atomicAdd(ecnt_out, cnt);
        base = __shfl_sync(0xffffffffu, base, 0);
        if (valid) {
            int p = base + __popc(m & ((1u << lane) - 1u));
            nes[p] = ns;
            ned[p] = nd;
            atomicAdd(&deg[nd], 1);
        }
    }
}

// ------------------ GCN kernels --------------------------------------------
// standalone: hd[n] = act(h[n]) @ W * dinv[n]   (INW4 = input width / 4)
template<int INW4, bool RELU>
__global__ void mm_kernel(const float4* __restrict__ h, const float* __restrict__ W,
                          const float* __restrict__ dinv, float4* __restrict__ hd, int N) {
    __shared__ float Ws[INW4*4*16];
    for (int i = threadIdx.x; i < INW4*4*16; i += blockDim.x) Ws[i] = W[i];
    __syncthreads();
    int n = blockIdx.x*blockDim.x + threadIdx.x;
    if (n >= N) return;
    float acc[16];
    #pragma unroll
    for (int j = 0; j < 16; j++) acc[j] = 0.f;
    const float4* hr = h + (size_t)n*INW4;
    #pragma unroll
    for (int q = 0; q < INW4; q++) {
        float4 v4 = hr[q];
        float vv[4] = {v4.x, v4.y, v4.z, v4.w};
        #pragma unroll
        for (int r = 0; r < 4; r++) {
            float v = RELU ? fmaxf(vv[r], 0.f) : vv[r];
            #pragma unroll
            for (int j = 0; j < 16; j++) acc[j] = fmaf(v, Ws[(q*4+r)*16+j], acc[j]);
        }
    }
    float dv = dinv[n];
    float4* o = hd + (size_t)n*4;
    #pragma unroll
    for (int q = 0; q < 4; q++)
        o[q] = make_float4(acc[q*4+0]*dv, acc[q*4+1]*dv, acc[q*4+2]*dv, acc[q*4+3]*dv);
}

// fused aggregate (+ optionally next layer's relu-matmul, or write h for pooling)
// h[n] = dinv[n]*(sum_{neighbors} hd[s] + hd[n]) + b
// if FUSE: hd_out[n] = relu(h[n]) @ Wn * dinv[n]
template<bool FUSE, bool WRITE_H>
__global__ void agg_fused(const float4* __restrict__ hd, const int* __restrict__ coff,
                          const int* __restrict__ deg, const int* __restrict__ col,
                          const float* __restrict__ dinv, const float* __restrict__ b,
                          const float* __restrict__ Wn,
                          float4* __restrict__ hd_out, float4* __restrict__ h_out, int N) {
    __shared__ float Ws[256];
    if (FUSE) {
        for (int i = threadIdx.x; i < 256; i += blockDim.x) Ws[i] = Wn[i];
        __syncthreads();
    }
    int warp = (blockIdx.x*blockDim.x + threadIdx.x) >> 5;
    int lane = threadIdx.x & 31;
    if (warp >= N) return;
    int n = warp;
    int c  = lane & 3;     // float4 slot (components 4c..4c+3)
    int e8 = lane >> 2;    // edge slot
    int start = coff[n];
    int cnt   = deg[n];
    float4 acc = make_float4(0.f, 0.f, 0.f, 0.f);
    for (int i = e8; i < cnt; i += 8) {
        int s = col[start + i];
        float4 v = hd[(size_t)s*4 + c];
        acc.x += v.x; acc.y += v.y; acc.z += v.z; acc.w += v.w;
    }
    #pragma unroll
    for (int off = 4; off <= 16; off <<= 1) {
        acc.x += __shfl_xor_sync(0xffffffffu, acc.x, off);
        acc.y += __shfl_xor_sync(0xffffffffu, acc.y, off);
        acc.z += __shfl_xor_sync(0xffffffffu, acc.z, off);
        acc.w += __shfl_xor_sync(0xffffffffu, acc.w, off);
    }
    float4 self = hd[(size_t)n*4 + c];
    float dv = dinv[n];
    float4 hv;
    hv.x = fmaf(dv, acc.x + self.x, b[4*c+0]);
    hv.y = fmaf(dv, acc.y + self.y, b[4*c+1]);
    hv.z = fmaf(dv, acc.z + self.z, b[4*c+2]);
    hv.w = fmaf(dv, acc.w + self.w, b[4*c+3]);
    if (WRITE_H && lane < 4) h_out[(size_t)n*4 + c] = hv;
    if (FUSE) {
        float od0 = 0.f, od1 = 0.f, od2 = 0.f, od3 = 0.f;
        #pragma unroll
        for (int i = 0; i < 16; i++) {
            float comp = ((i & 3) == 0) ? hv.x : ((i & 3) == 1) ? hv.y :
                         ((i & 3) == 2) ? hv.z : hv.w;
            float hi = __shfl_sync(0xffffffffu, comp, i >> 2);
            hi = fmaxf(hi, 0.f);
            od0 = fmaf(hi, Ws[i*16 + 4*c + 0], od0);
            od1 = fmaf(hi, Ws[i*16 + 4*c + 1], od1);
            od2 = fmaf(hi, Ws[i*16 + 4*c + 2], od2);
            od3 = fmaf(hi, Ws[i*16 + 4*c + 3], od3);
        }
        if (lane < 4)
            hd_out[(size_t)n*4 + c] = make_float4(od0*dv, od1*dv, od2*dv, od3*dv);
    }
}

// ------------------ top-k pooling ------------------------------------------
template<int NPGv, int Kv, int Pv>
__global__ void pool_kernel(const float4* __restrict__ h, const float* __restrict__ w,
                            float4* __restrict__ hout, int* __restrict__ np) {
    __shared__ float skey[Pv];
    __shared__ int   sidx[Pv];
    int bG = blockIdx.x;
    int tid = threadIdx.x;
    const int T = 1024;
    float wn = 0.f;
    float wv[16];
    #pragma unroll
    for (int j = 0; j < 16; j++) { wv[j] = w[j]; wn = fmaf(wv[j], wv[j], wn); }
    wn = sqrtf(wn);
    for (int i = tid; i < Pv; i += T) {
        if (i < NPGv) {
            const float4* hr = h + ((size_t)bG*NPGv + i)*4;
            float s = 0.f;
            #pragma unroll
            for (int q = 0; q < 4; q++) {
                float4 v = hr[q];
                s = fmaf(v.x, wv[q*4+0], s);
                s = fmaf(v.y, wv[q*4+1], s);
                s = fmaf(v.z, wv[q*4+2], s);
                s = fmaf(v.w, wv[q*4+3], s);
            }
            skey[i] = s/wn;
        } else {
            skey[i] = -FLT_MAX;
        }
        sidx[i] = i;
    }
    __syncthreads();
    for (int size = 2; size <= Pv; size <<= 1) {
        for (int stride = size >> 1; stride > 0; stride >>= 1) {
            for (int i = tid; i < Pv; i += T) {
                int p = i ^ stride;
                if (p > i) {
                    bool desc = ((i & size) == 0);
                    float a = skey[i], cc = skey[p];
                    bool sw = desc ? (a < cc) : (a > cc);
                    if (sw) {
                        skey[i] = cc; skey[p] = a;
                        int t = sidx[i]; sidx[i] = sidx[p]; sidx[p] = t;
                    }
                }
            }
            __syncthreads();
        }
    }
    for (int i = tid; i < NPGv; i += T) np[bG*NPGv + i] = -1;
    __syncthreads();
    for (int j = tid; j < Kv; j += T) np[bG*NPGv + sidx[j]] = bG*Kv + j;
    for (int t = tid; t < Kv*4; t += T) {
        int j = t >> 2, q = t & 3;
        float gate = tanhf(skey[j]);
        float4 v = h[((size_t)bG*NPGv + sidx[j])*4 + q];
        hout[((size_t)bG*Kv + j)*4 + q] =
            make_float4(v.x*gate, v.y*gate, v.z*gate, v.w*gate);
    }
}

// ------------------ final mean-pool + linear --------------------------------
__global__ void final_kernel(const float4* __restrict__ h, const float* __restrict__ linW,
                             const float* __restrict__ linb, float* __restrict__ out) {
    __shared__ float sh[128*16];
    int bG = blockIdx.x, tid = threadIdx.x;
    float acc[16];
    #pragma unroll
    for (int j = 0; j < 16; j++) acc[j] = 0.f;
    for (int r = tid; r < KK3; r += 128) {
        const float4* hr = h + ((size_t)bG*KK3 + r)*4;
        #pragma unroll
        for (int q = 0; q < 4; q++) {
            float4 v = hr[q];
            acc[q*4+0] += v.x; acc[q*4+1] += v.y;
            acc[q*4+2] += v.z; acc[q*4+3] += v.w;
        }
    }
    #pragma unroll
    for (int j = 0; j < 16; j++) sh[tid*16+j] = acc[j];
    __syncthreads();
    for (int s = 64; s > 0; s >>= 1) {
        if (tid < s) {
            #pragma unroll
            for (int j = 0; j < 16; j++) sh[tid*16+j] += sh[(tid+s)*16+j];
        }
        __syncthreads();
    }
    if (tid < OUTD) {
        float r = linb[tid];
        #pragma unroll
        for (int j = 0; j < 16; j++) r = fmaf(sh[j]/(float)KK3, linW[j*OUTD+tid], r);
        out[bG*OUTD + tid] = r;
    }
}

// ------------------ host orchestration -------------------------------------
static void run_scan(int N, int* deg, int* coff, int* cur, float* dinv, int* bsums) {
    int nb = (N + 1023)/1024;
    scan_block_kernel<<<nb, 1024>>>(deg, coff, bsums, N);
    scan_sums_kernel<<<1, 128>>>(bsums);
    finalize_kernel<<<nb, 1024>>>(coff, cur, dinv, deg, bsums, N);
}

extern "C" void kernel_launch(void* const* d_in, const int* in_sizes, int n_in,
                              void* d_out, int out_size) {
    const int*   x      = (const int*)  d_in[0];
    const int*   ei     = (const int*)  d_in[1];
    const float* eg     = (const float*)d_in[3];
    const float* ea     = (const float*)d_in[4];
    const float* firstW = (const float*)d_in[5];
    const float* firstb = (const float*)d_in[6];
    const float* Ws     = (const float*)d_in[7];
    const float* bs     = (const float*)d_in[8];
    const float* poolw  = (const float*)d_in[9];
    const float* linW   = (const float*)d_in[10];
    const float* linb   = (const float*)d_in[11];
    float* out = (float*)d_out;

    float *h24, *hdA, *hdB, *hP, *dinv;
    int *esrc, *edst, *esrc2, *edst2, *col, *coff, *cur, *deg, *np, *bsums, *ecnt;
    cudaGetSymbolAddress((void**)&h24,  g_h24);
    cudaGetSymbolAddress((void**)&hdA,  g_hdA);
    cudaGetSymbolAddress((void**)&hdB,  g_hdB);
    cudaGetSymbolAddress((void**)&hP,   g_hP);
    cudaGetSymbolAddress((void**)&dinv, g_dinv);
    cudaGetSymbolAddress((void**)&esrc, g_esrc);
    cudaGetSymbolAddress((void**)&edst, g_edst);
    cudaGetSymbolAddress((void**)&esrc2,g_esrc2);
    cudaGetSymbolAddress((void**)&edst2,g_edst2);
    cudaGetSymbolAddress((void**)&col,  g_col);
    cudaGetSymbolAddress((void**)&coff, g_coff);
    cudaGetSymbolAddress((void**)&cur,  g_cur);
    cudaGetSymbolAddress((void**)&deg,  g_deg);
    cudaGetSymbolAddress((void**)&np,   g_np);
    cudaGetSymbolAddress((void**)&bsums,g_bsums);
    cudaGetSymbolAddress((void**)&ecnt, g_ecnt);

    const int* ei_src = ei;
    const int* ei_dst = ei + E_TOT;

    feat_kernel<<<(N0+127)/128, 128>>>(x, (const float4*)eg, (const float4*)ea,
                                       (float4*)h24);

    // ---- CSR level 0 (edges straight from input) ----
    cudaMemsetAsync(deg, 0, (size_t)N0*sizeof(int));
    cudaMemsetAsync(bsums, 0, 128*sizeof(int));
    hist0_kernel<<<2048, 512>>>(ei_dst, deg);
    run_scan(N0, deg, coff, cur, dinv, bsums);
    scatter_kernel<<<2048, 512>>>(ei_src, ei_dst, cur, col, E_TOT, nullptr);

    // ---- block 0: first GCN (24->16) + 5 layers ----
    mm_kernel<6, false><<<(N0+127)/128, 128>>>((const float4*)h24, firstW, dinv,
                                               (float4*)hdA, N0);
    agg_fused<true,false><<<(N0+7)/8, 256>>>((const float4*)hdA, coff, deg, col, dinv,
                                             firstb, Ws + 0, (float4*)hdB, nullptr, N0);
    agg_fused<true,false><<<(N0+7)/8, 256>>>((const float4*)hdB, coff, deg, col, dinv,
                                             bs + 0*16, Ws + 1*256, (float4*)hdA, nullptr, N0);
    agg_fused<true,false><<<(N0+7)/8, 256>>>((const float4*)hdA, coff, deg, col, dinv,
                                             bs + 1*16, Ws + 2*256, (float4*)hdB, nullptr, N0);
    agg_fused<true,false><<<(N0+7)/8, 256>>>((const float4*)hdB, coff, deg, col, dinv,
                                             bs + 2*16, Ws + 3*256, (float4*)hdA, nullptr, N0);
    agg_fused<true,false><<<(N0+7)/8, 256>>>((const float4*)hdA, coff, deg, col, dinv,
                                             bs + 3*16, Ws + 4*256, (float4*)hdB, nullptr, N0);
    agg_fused<false,true><<<(N0+7)/8, 256>>>((const float4*)hdB, coff, deg, col, dinv,
                                             bs + 4*16, nullptr, nullptr, (float4*)hP, N0);

    pool_kernel<NPG0, KK1, 4096><<<BB, 1024>>>((const float4*)hP, poolw + 0,
                                               (float4*)h24, np);

    // ---- CSR level 1 (remap+compact from input edges) ----
    cudaMemsetAsync(deg, 0, (size_t)NN1*sizeof(int));
    cudaMemsetAsync(bsums, 0, 128*sizeof(int));
    cudaMemsetAsync(ecnt, 0, sizeof(int));
    remap_compact<<<2048, 512>>>(ei_src, ei_dst, E_TOT, nullptr, np,
                                 esrc, edst, deg, ecnt);
    run_scan(NN1, deg, coff, cur, dinv, bsums);
    scatter_kernel<<<2048, 512>>>(esrc, edst, cur, col, 0, ecnt);

    // ---- block 1 ----
    mm_kernel<4, true><<<(NN1+127)/128, 128>>>((const float4*)h24, Ws + 5*256, dinv,
                                               (float4*)hdA, NN1);
    agg_fused<true,false><<<(NN1+7)/8, 256>>>((const float4*)hdA, coff, deg, col, dinv,
                                              bs + 5*16, Ws + 6*256, (float4*)hdB, nullptr, NN1);
    agg_fused<true,false><<<(NN1+7)/8, 256>>>((const float4*)hdB, coff, deg, col, dinv,
                                              bs + 6*16, Ws + 7*256, (float4*)hdA, nullptr, NN1);
    agg_fused<true,false><<<(NN1+7)/8, 256>>>((const float4*)hdA, coff, deg, col, dinv,
                                              bs + 7*16, Ws + 8*256, (float4*)hdB, nullptr, NN1);
    agg_fused<true,false><<<(NN1+7)/8, 256>>>((const float4*)hdB, coff, deg, col, dinv,
                                              bs + 8*16, Ws + 9*256, (float4*)hdA, nullptr, NN1);
    agg_fused<false,true><<<(NN1+7)/8, 256>>>((const float4*)hdA, coff, deg, col, dinv,
                                              bs + 9*16, nullptr, nullptr, (float4*)hP, NN1);

    pool_kernel<KK1, KK2, 4096><<<BB, 1024>>>((const float4*)hP, poolw + 16,
                                              (float4*)h24, np);

    // ---- CSR level 2 ----
    cudaMemsetAsync(deg, 0, (size_t)NN2*sizeof(int));
    cudaMemsetAsync(bsums, 0, 128*sizeof(int));
    // keep level-1 count in a register-free way: remap reads old ecnt BEFORE we zero it,
    // so use a second counter strategy: copy old count via separate symbol read order.
    // Simpler: run remap first (reads ecnt), then zero ecnt is wrong. So: remap writes to
    // a fresh counter. We re-purpose bsums[127] slot? No — use ordering below instead.
    remap_compact<<<2048, 512>>>(esrc, edst, 0, ecnt, np, esrc2, edst2, deg, bsums + 64);
    // bsums[64..] zeroed above; bsums[64] acts as ecnt2 (outside the 128-scan? it IS
    // inside. Fix: copy into ecnt afterwards and re-zero bsums region before scan.)
    cudaMemcpyAsync(ecnt, bsums + 64, sizeof(int), cudaMemcpyDeviceToDevice);
    cudaMemsetAsync(bsums, 0, 128*sizeof(int));
    run_scan(NN2, deg, coff, cur, dinv, bsums);
    scatter_kernel<<<2048, 512>>>(esrc2, edst2, cur, col, 0, ecnt);

    // ---- block 2 ----
    mm_kernel<4, true><<<(NN2+127)/128, 128>>>((const float4*)h24, Ws + 10*256, dinv,
                                               (float4*)hdA, NN2);
    agg_fused<true,false><<<(NN2+7)/8, 256>>>((const float4*)hdA, coff, deg, col, dinv,
                                              bs + 10*16, Ws + 11*256, (float4*)hdB, nullptr, NN2);
    agg_fused<true,false><<<(NN2+7)/8, 256>>>((const float4*)hdB, coff, deg, col, dinv,
                                              bs + 11*16, Ws + 12*256, (float4*)hdA, nullptr, NN2);
    agg_fused<true,false><<<(NN2+7)/8, 256>>>((const float4*)hdA, coff, deg, col, dinv,
                                              bs + 12*16, Ws + 13*256, (float4*)hdB, nullptr, NN2);
    agg_fused<true,false><<<(NN2+7)/8, 256>>>((const float4*)hdB, coff, deg, col, dinv,
                                              bs + 13*16, Ws + 14*256, (float4*)hdA, nullptr, NN2);
    agg_fused<false,true><<<(NN2+7)/8, 256>>>((const float4*)hdA, coff, deg, col, dinv,
                                              bs + 14*16, nullptr, nullptr, (float4*)hP, NN2);

    pool_kernel<KK2, KK3, 2048><<<BB, 1024>>>((const float4*)hP, poolw + 32,
                                              (float4*)h24, np);

    final_kernel<<<BB, 128>>>((const float4*)h24, linW, linb, out);
}

// round 7
// speedup vs baseline: 1.3645x; 1.3645x over previous
#include <cuda_runtime.h>
#include <math.h>
#include <float.h>

#define BB 32
#define NPG0 4096
#define OUTD 23
#define N0 131072
#define E_TOT (N0*16)
#define KK1 2458
#define NN1 (BB*KK1)
#define KK2 1475
#define NN2 (BB*KK2)
#define KK3 885
#define NN3 (BB*KK3)
#define DIVC 1.0e-4f

// ------------------ scratch (device globals; zero-initialized at load) -----
__device__ float g_hdA [N0*16];
__device__ float g_hdB [N0*16];
__device__ float g_hPre[N0*16];     // h written before pooling
__device__ float g_hPool[NN1*16];   // pooled h
__device__ float g_dinv[N0];
__device__ int   g_esrc [E_TOT];
__device__ int   g_edst [E_TOT];
__device__ int   g_esrc2[E_TOT/2];
__device__ int   g_edst2[E_TOT/2];
__device__ int   g_col [E_TOT];
__device__ int   g_coff[N0];
__device__ int   g_cur [N0];
__device__ int   g_deg [N0];        // must be zero at start of each replay
__device__ int   g_np  [N0];
__device__ int   g_bsums[160];
__device__ int   g_ecnt;            // zeroed by pool1 each replay
__device__ int   g_ecnt2;           // zeroed by pool2 each replay

// ------------------ CSR build ----------------------------------------------
__global__ void hist0_kernel(const int* __restrict__ edst, int* __restrict__ deg) {
    for (int e = blockIdx.x*blockDim.x + threadIdx.x; e < E_TOT; e += gridDim.x*blockDim.x)
        atomicAdd(&deg[edst[e]], 1);
}

__global__ void scan_block_kernel(const int* __restrict__ in, int* __restrict__ out,
                                  int* __restrict__ bsums, int N) {
    __shared__ int sh[1024];
    int tid = threadIdx.x;
    int gid = blockIdx.x*1024 + tid;
    int v = (gid < N) ? in[gid] : 0;
    sh[tid] = v;
    __syncthreads();
    for (int off = 1; off < 1024; off <<= 1) {
        int t = (tid >= off) ? sh[tid-off] : 0;
        __syncthreads();
        sh[tid] += t;
        __syncthreads();
    }
    if (gid < N) out[gid] = sh[tid] - v;
    if (tid == 1023) bsums[blockIdx.x] = sh[1023];
}

// finalize: each block redundantly sums bsums[0..bid) (<=128 values)
__global__ void finalize_kernel(int* __restrict__ coff, int* __restrict__ cur,
                                float* __restrict__ dinv, const int* __restrict__ deg,
                                const int* __restrict__ bsums, int N) {
    __shared__ int s_prefix;
    int bid = blockIdx.x;
    if (threadIdx.x < 32) {
        int acc = 0;
        for (int k = threadIdx.x; k < bid; k += 32) acc += bsums[k];
        #pragma unroll
        for (int o = 16; o; o >>= 1) acc += __shfl_xor_sync(0xffffffffu, acc, o);
        if (threadIdx.x == 0) s_prefix = acc;
    }
    __syncthreads();
    int n = bid*1024 + threadIdx.x;
    if (n >= N) return;
    int off = coff[n] + s_prefix;
    coff[n] = off;
    cur[n]  = off;
    dinv[n] = rsqrtf((float)deg[n] + 1.0f);
}

__global__ void scatter_kernel(const int* __restrict__ es, const int* __restrict__ ed,
                               int* __restrict__ cur, int* __restrict__ col,
                               int Efixed, const int* __restrict__ ecnt) {
    int E = ecnt ? *ecnt : Efixed;
    for (int e = blockIdx.x*blockDim.x + threadIdx.x; e < E; e += gridDim.x*blockDim.x) {
        int d = ed[e];
        int p = atomicAdd(&cur[d], 1);
        col[p] = es[e];
    }
}

// remap + compact + degree-hist fused (warp-aggregated counter)
__global__ void remap_compact(const int* __restrict__ es, const int* __restrict__ ed,
                              int Efixed, const int* __restrict__ ecnt_in,
                              const int* __restrict__ np,
                              int* __restrict__ nes, int* __restrict__ ned,
                              int* __restrict__ deg, int* __restrict__ ecnt_out) {
    int E = ecnt_in ? *ecnt_in : Efixed;
    int lane = threadIdx.x & 31;
    int idx = blockIdx.x*blockDim.x + threadIdx.x;
    int stride = gridDim.x*blockDim.x;
    for (int e = idx; e - lane < E; e += stride) {
        bool valid = false;
        int ns = 0, nd = 0;
        if (e < E) {
            ns = np[es[e]];
            nd = np[ed[e]];
            valid = (ns >= 0) && (nd >= 0);
        }
        unsigned m = __ballot_sync(0xffffffffu, valid);
        int cnt = __popc(m);
        int base = 0;
        if (lane == 0 && cnt) base = atomicAdd(ecnt_out, cnt);
        base = __shfl_sync(0xffffffffu, base, 0);
        if (valid) {
            int p = base + __popc(m & ((1u << lane) - 1u));
            nes[p] = ns;
            ned[p] = nd;
            atomicAdd(&deg[nd], 1);
        }
    }
}

// ------------------ feature build fused with first matmul ------------------
// hd[n] = (features(n) @ firstW) * dinv[n]
__global__ void featmm_kernel(const int* __restrict__ x, const float4* __restrict__ eg4,
                              const float4* __restrict__ ea4, const float* __restrict__ W,
                              const float* __restrict__ dinv, float4* __restrict__ hd) {
    __shared__ float Ws[24*16];
    for (int i = threadIdx.x; i < 24*16; i += blockDim.x) Ws[i] = W[i];
    __syncthreads();
    int n = blockIdx.x*blockDim.x + threadIdx.x;   // N0 divisible by blockDim
    int g = x[n*4+0];
    int a = x[n*4+3];
    float f[24];
    {
        const float4* gr = eg4 + (size_t)g*4;
        #pragma unroll
        for (int q = 0; q < 4; q++) {
            float4 v = gr[q];
            f[q*4+0] = v.x; f[q*4+1] = v.y; f[q*4+2] = v.z; f[q*4+3] = v.w;
        }
    }
    #pragma unroll
    for (int c = 0; c < 2; c++) {
        int j = 2*n + c;
        if (j < N0) {
            f[16+c] = sinf((float)x[j*4+1]*DIVC);
            f[18+c] = sinf((float)x[j*4+2]*DIVC);
        } else {
            int jj = j - N0;
            f[16+c] = cosf((float)x[jj*4+1]*DIVC);
            f[18+c] = cosf((float)x[jj*4+2]*DIVC);
        }
    }
    {
        float4 av = ea4[a];
        f[20] = av.x; f[21] = av.y; f[22] = av.z; f[23] = av.w;
    }
    float acc[16];
    #pragma unroll
    for (int j = 0; j < 16; j++) acc[j] = 0.f;
    #pragma unroll
    for (int i = 0; i < 24; i++) {
        float v = f[i];
        #pragma unroll
        for (int j = 0; j < 16; j++) acc[j] = fmaf(v, Ws[i*16+j], acc[j]);
    }
    float dv = dinv[n];
    float4* o = hd + (size_t)n*4;
    #pragma unroll
    for (int q = 0; q < 4; q++)
        o[q] = make_float4(acc[q*4+0]*dv, acc[q*4+1]*dv, acc[q*4+2]*dv, acc[q*4+3]*dv);
}

// ------------------ standalone matmul (pooled h -> hd) ----------------------
__global__ void mm16_kernel(const float4* __restrict__ h, const float* __restrict__ W,
                            const float* __restrict__ dinv, float4* __restrict__ hd, int N) {
    __shared__ float Ws[256];
    for (int i = threadIdx.x; i < 256; i += blockDim.x) Ws[i] = W[i];
    __syncthreads();
    int n = blockIdx.x*blockDim.x + threadIdx.x;
    if (n >= N) return;
    float acc[16];
    #pragma unroll
    for (int j = 0; j < 16; j++) acc[j] = 0.f;
    const float4* hr = h + (size_t)n*4;
    #pragma unroll
    for (int q = 0; q < 4; q++) {
        float4 v4 = hr[q];
        float vv[4] = {v4.x, v4.y, v4.z, v4.w};
        #pragma unroll
        for (int r = 0; r < 4; r++) {
            float v = fmaxf(vv[r], 0.f);
            #pragma unroll
            for (int j = 0; j < 16; j++) acc[j] = fmaf(v, Ws[(q*4+r)*16+j], acc[j]);
        }
    }
    float dv = dinv[n];
    float4* o = hd + (size_t)n*4;
    #pragma unroll
    for (int q = 0; q < 4; q++)
        o[q] = make_float4(acc[q*4+0]*dv, acc[q*4+1]*dv, acc[q*4+2]*dv, acc[q*4+3]*dv);
}

// ------------------ fused aggregate (+ optional next-layer matmul via smem) -
// h[n] = dinv[n]*(sum_neigh hd[s] + hd[n]) + b
// FUSE:    hd_out[n] = relu(h[n]) @ Wn * dinv[n]
// WRITE_H: h_out[n]  = h[n]
// N must be divisible by 8 (grid = N/8 blocks of 256).
template<bool FUSE, bool WRITE_H>
__global__ void __launch_bounds__(256)
agg_fused(const float4* __restrict__ hd, const int* __restrict__ coff,
          const int* __restrict__ deg, const int* __restrict__ col,
          const float* __restrict__ dinv, const float* __restrict__ b,
          const float* __restrict__ Wn,
          float* __restrict__ hd_out, float4* __restrict__ h_out, int N) {
    __shared__ float Ws[256];
    __shared__ float hv_s[8][17];
    __shared__ float dv_s[8];
    if (FUSE) {
        for (int i = threadIdx.x; i < 256; i += blockDim.x) Ws[i] = Wn[i];
    }
    int w    = threadIdx.x >> 5;
    int lane = threadIdx.x & 31;
    int n = blockIdx.x*8 + w;
    int c  = lane & 3;     // float4 slot
    int e8 = lane >> 2;    // edge slot
    int start = coff[n];
    int cnt   = deg[n];
    float4 acc = make_float4(0.f, 0.f, 0.f, 0.f);
    for (int i = e8; i < cnt; i += 8) {
        int s = __ldg(col + start + i);
        float4 v = __ldg(hd + (size_t)s*4 + c);
        acc.x += v.x; acc.y += v.y; acc.z += v.z; acc.w += v.w;
    }
    #pragma unroll
    for (int off = 4; off <= 16; off <<= 1) {
        acc.x += __shfl_xor_sync(0xffffffffu, acc.x, off);
        acc.y += __shfl_xor_sync(0xffffffffu, acc.y, off);
        acc.z += __shfl_xor_sync(0xffffffffu, acc.z, off);
        acc.w += __shfl_xor_sync(0xffffffffu, acc.w, off);
    }
    float dv = dinv[n];
    if (lane < 4) {
        float4 self = hd[(size_t)n*4 + c];
        float4 hv;
        hv.x = fmaf(dv, acc.x + self.x, b[4*c+0]);
        hv.y = fmaf(dv, acc.y + self.y, b[4*c+1]);
        hv.z = fmaf(dv, acc.z + self.z, b[4*c+2]);
        hv.w = fmaf(dv, acc.w + self.w, b[4*c+3]);
        if (WRITE_H) h_out[(size_t)n*4 + c] = hv;
        if (FUSE) {
            hv_s[w][4*c+0] = hv.x; hv_s[w][4*c+1] = hv.y;
            hv_s[w][4*c+2] = hv.z; hv_s[w][4*c+3] = hv.w;
            if (lane == 0) dv_s[w] = dv;
        }
    }
    if (FUSE) {
        __syncthreads();
        int tid = threadIdx.x;
        if (tid < 128) {
            int ww = tid >> 4, j = tid & 15;
            float a2 = 0.f;
            #pragma unroll
            for (int i = 0; i < 16; i++)
                a2 = fmaf(fmaxf(hv_s[ww][i], 0.f), Ws[i*16+j], a2);
            int n2 = blockIdx.x*8 + ww;
            hd_out[(size_t)n2*16 + j] = a2 * dv_s[ww];
        }
    }
}

// ------------------ top-k pooling (+ zero next level's deg/counter) ---------
template<int NPGv, int Kv, int Pv>
__global__ void pool_kernel(const float4* __restrict__ h, const float* __restrict__ w,
                            float4* __restrict__ hout, int* __restrict__ np,
                            int* __restrict__ deg_zero, int degN_per_blk,
                            int* __restrict__ cnt_zero) {
    __shared__ float skey[Pv];
    __shared__ int   sidx[Pv];
    int bG = blockIdx.x;
    int tid = threadIdx.x;
    const int T = 1024;
    // zero next level's deg slice + counter (used only after this kernel)
    if (deg_zero) {
        for (int i = tid; i < degN_per_blk; i += T) deg_zero[bG*degN_per_blk + i] = 0;
        if (bG == 0 && tid == 0) *cnt_zero = 0;
    }
    float wn = 0.f;
    float wv[16];
    #pragma unroll
    for (int j = 0; j < 16; j++) { wv[j] = w[j]; wn = fmaf(wv[j], wv[j], wn); }
    wn = sqrtf(wn);
    for (int i = tid; i < Pv; i += T) {
        if (i < NPGv) {
            const float4* hr = h + ((size_t)bG*NPGv + i)*4;
            float s = 0.f;
            #pragma unroll
            for (int q = 0; q < 4; q++) {
                float4 v = hr[q];
                s = fmaf(v.x, wv[q*4+0], s);
                s = fmaf(v.y, wv[q*4+1], s);
                s = fmaf(v.z, wv[q*4+2], s);
                s = fmaf(v.w, wv[q*4+3], s);
            }
            skey[i] = s/wn;
        } else {
            skey[i] = -FLT_MAX;
        }
        sidx[i] = i;
    }
    __syncthreads();
    for (int size = 2; size <= Pv; size <<= 1) {
        for (int stride = size >> 1; stride > 0; stride >>= 1) {
            for (int i = tid; i < Pv; i += T) {
                int p = i ^ stride;
                if (p > i) {
                    bool desc = ((i & size) == 0);
                    float a = skey[i], cc = skey[p];
                    bool sw = desc ? (a < cc) : (a > cc);
                    if (sw) {
                        skey[i] = cc; skey[p] = a;
                        int t = sidx[i]; sidx[i] = sidx[p]; sidx[p] = t;
                    }
                }
            }
            __syncthreads();
        }
    }
    for (int i = tid; i < NPGv; i += T) np[bG*NPGv + i] = -1;
    __syncthreads();
    for (int j = tid; j < Kv; j += T) np[bG*NPGv + sidx[j]] = bG*Kv + j;
    for (int t = tid; t < Kv*4; t += T) {
        int j = t >> 2, q = t & 3;
        float gate = tanhf(skey[j]);
        float4 v = h[((size_t)bG*NPGv + sidx[j])*4 + q];
        hout[((size_t)bG*Kv + j)*4 + q] =
            make_float4(v.x*gate, v.y*gate, v.z*gate, v.w*gate);
    }
}

// ------------------ final mean-pool + linear (+ re-zero deg for next replay)
__global__ void final_kernel(const float4* __restrict__ h, const float* __restrict__ linW,
                             const float* __restrict__ linb, float* __restrict__ out,
                             int* __restrict__ deg_zero) {
    __shared__ float sh[128*16];
    int bG = blockIdx.x, tid = threadIdx.x;
    // re-establish replay invariant: deg[0..N0) == 0
    for (int i = bG*128 + tid; i < N0; i += 32*128) deg_zero[i] = 0;
    float acc[16];
    #pragma unroll
    for (int j = 0; j < 16; j++) acc[j] = 0.f;
    for (int r = tid; r < KK3; r += 128) {
        const float4* hr = h + ((size_t)bG*KK3 + r)*4;
        #pragma unroll
        for (int q = 0; q < 4; q++) {
            float4 v = hr[q];
            acc[q*4+0] += v.x; acc[q*4+1] += v.y;
            acc[q*4+2] += v.z; acc[q*4+3] += v.w;
        }
    }
    #pragma unroll
    for (int j = 0; j < 16; j++) sh[tid*16+j] = acc[j];
    __syncthreads();
    for (int s = 64; s > 0; s >>= 1) {
        if (tid < s) {
            #pragma unroll
            for (int j = 0; j < 16; j++) sh[tid*16+j] += sh[(tid+s)*16+j];
        }
        __syncthreads();
    }
    if (tid < OUTD) {
        float r = linb[tid];
        #pragma unroll
        for (int j = 0; j < 16; j++) r = fmaf(sh[j]/(float)KK3, linW[j*OUTD+tid], r);
        out[bG*OUTD + tid] = r;
    }
}

// ------------------ host orchestration -------------------------------------
extern "C" void kernel_launch(void* const* d_in, const int* in_sizes, int n_in,
                              void* d_out, int out_size) {
    const int*   x      = (const int*)  d_in[0];
    const int*   ei     = (const int*)  d_in[1];
    const float* eg     = (const float*)d_in[3];
    const float* ea     = (const float*)d_in[4];
    const float* firstW = (const float*)d_in[5];
    const float* firstb = (const float*)d_in[6];
    const float* Ws     = (const float*)d_in[7];
    const float* bs     = (const float*)d_in[8];
    const float* poolw  = (const float*)d_in[9];
    const float* linW   = (const float*)d_in[10];
    const float* linb   = (const float*)d_in[11];
    float* out = (float*)d_out;

    float *hdA, *hdB, *hPre, *hPool, *dinv;
    int *esrc, *edst, *esrc2, *edst2, *col, *coff, *cur, *deg, *np, *bsums, *ecnt, *ecnt2;
    cudaGetSymbolAddress((void**)&hdA,  g_hdA);
    cudaGetSymbolAddress((void**)&hdB,  g_hdB);
    cudaGetSymbolAddress((void**)&hPre, g_hPre);
    cudaGetSymbolAddress((void**)&hPool,g_hPool);
    cudaGetSymbolAddress((void**)&dinv, g_dinv);
    cudaGetSymbolAddress((void**)&esrc, g_esrc);
    cudaGetSymbolAddress((void**)&edst, g_edst);
    cudaGetSymbolAddress((void**)&esrc2,g_esrc2);
    cudaGetSymbolAddress((void**)&edst2,g_edst2);
    cudaGetSymbolAddress((void**)&col,  g_col);
    cudaGetSymbolAddress((void**)&coff, g_coff);
    cudaGetSymbolAddress((void**)&cur,  g_cur);
    cudaGetSymbolAddress((void**)&deg,  g_deg);
    cudaGetSymbolAddress((void**)&np,   g_np);
    cudaGetSymbolAddress((void**)&bsums,g_bsums);
    cudaGetSymbolAddress((void**)&ecnt, g_ecnt);
    cudaGetSymbolAddress((void**)&ecnt2,g_ecnt2);

    const int* ei_src = ei;
    const int* ei_dst = ei + E_TOT;

    // ---- CSR level 0 (deg pre-zeroed: load-time init / previous replay's final) ----
    hist0_kernel<<<2048, 512>>>(ei_dst, deg);                                   // 0
    scan_block_kernel<<<128, 1024>>>(deg, coff, bsums, N0);                     // 1
    finalize_kernel<<<128, 1024>>>(coff, cur, dinv, deg, bsums, N0);            // 2
    scatter_kernel<<<2048, 512>>>(ei_src, ei_dst, cur, col, E_TOT, nullptr);    // 3

    // ---- block 0 ----
    featmm_kernel<<<N0/128, 128>>>(x, (const float4*)eg, (const float4*)ea,
                                   firstW, dinv, (float4*)hdA);                 // 4
    agg_fused<true,false><<<N0/8, 256>>>((const float4*)hdA, coff, deg, col, dinv,
                    firstb, Ws + 0*256, hdB, nullptr, N0);                      // 5 (profiled)
    agg_fused<true,false><<<N0/8, 256>>>((const float4*)hdB, coff, deg, col, dinv,
                    bs + 0*16, Ws + 1*256, hdA, nullptr, N0);
    agg_fused<true,false><<<N0/8, 256>>>((const float4*)hdA, coff, deg, col, dinv,
                    bs + 1*16, Ws + 2*256, hdB, nullptr, N0);
    agg_fused<true,false><<<N0/8, 256>>>((const float4*)hdB, coff, deg, col, dinv,
                    bs + 2*16, Ws + 3*256, hdA, nullptr, N0);
    agg_fused<true,false><<<N0/8, 256>>>((const float4*)hdA, coff, deg, col, dinv,
                    bs + 3*16, Ws + 4*256, hdB, nullptr, N0);
    agg_fused<false,true><<<N0/8, 256>>>((const float4*)hdB, coff, deg, col, dinv,
                    bs + 4*16, nullptr, nullptr, (float4*)hPre, N0);

    pool_kernel<NPG0, KK1, 4096><<<BB, 1024>>>((const float4*)hPre, poolw + 0,
                    (float4*)hPool, np, deg, KK1, ecnt);

    // ---- CSR level 1 ----
    remap_compact<<<2048, 512>>>(ei_src, ei_dst, E_TOT, nullptr, np,
                                 esrc, edst, deg, ecnt);
    scan_block_kernel<<<(NN1+1023)/1024, 1024>>>(deg, coff, bsums, NN1);
    finalize_kernel<<<(NN1+1023)/1024, 1024>>>(coff, cur, dinv, deg, bsums, NN1);
    scatter_kernel<<<2048, 512>>>(esrc, edst, cur, col, 0, ecnt);

    // ---- block 1 ----
    mm16_kernel<<<(NN1+127)/128, 128>>>((const float4*)hPool, Ws + 5*256, dinv,
                                        (float4*)hdA, NN1);
    agg_fused<true,false><<<NN1/8, 256>>>((const float4*)hdA, coff, deg, col, dinv,
                    bs + 5*16, Ws + 6*256, hdB, nullptr, NN1);
    agg_fused<true,false><<<NN1/8, 256>>>((const float4*)hdB, coff, deg, col, dinv,
                    bs + 6*16, Ws + 7*256, hdA, nullptr, NN1);
    agg_fused<true,false><<<NN1/8, 256>>>((const float4*)hdA, coff, deg, col, dinv,
                    bs + 7*16, Ws + 8*256, hdB, nullptr, NN1);
    agg_fused<true,false><<<NN1/8, 256>>>((const float4*)hdB, coff, deg, col, dinv,
                    bs + 8*16, Ws + 9*256, hdA, nullptr, NN1);
    agg_fused<false,true><<<NN1/8, 256>>>((const float4*)hdA, coff, deg, col, dinv,
                    bs + 9*16, nullptr, nullptr, (float4*)hPre, NN1);

    pool_kernel<KK1, KK2, 4096><<<BB, 1024>>>((const float4*)hPre, poolw + 16,
                    (float4*)hPool, np, deg, KK2, ecnt2);

    // ---- CSR level 2 ----
    remap_compact<<<2048, 512>>>(esrc, edst, 0, ecnt, np,
                                 esrc2, edst2, deg, ecnt2);
    scan_block_kernel<<<(NN2+1023)/1024, 1024>>>(deg, coff, bsums, NN2);
    finalize_kernel<<<(NN2+1023)/1024, 1024>>>(coff, cur, dinv, deg, bsums, NN2);
    scatter_kernel<<<2048, 512>>>(esrc2, edst2, cur, col, 0, ecnt2);

    // ---- block 2 ----
    mm16_kernel<<<(NN2+127)/128, 128>>>((const float4*)hPool, Ws + 10*256, dinv,
                                        (float4*)hdA, NN2);
    agg_fused<true,false><<<NN2/8, 256>>>((const float4*)hdA, coff, deg, col, dinv,
                    bs + 10*16, Ws + 11*256, hdB, nullptr, NN2);
    agg_fused<true,false><<<NN2/8, 256>>>((const float4*)hdB, coff, deg, col, dinv,
                    bs + 11*16, Ws + 12*256, hdA, nullptr, NN2);
    agg_fused<true,false><<<NN2/8, 256>>>((const float4*)hdA, coff, deg, col, dinv,
                    bs + 12*16, Ws + 13*256, hdB, nullptr, NN2);
    agg_fused<true,false><<<NN2/8, 256>>>((const float4*)hdB, coff, deg, col, dinv,
                    bs + 13*16, Ws + 14*256, hdA, nullptr, NN2);
    agg_fused<false,true><<<NN2/8, 256>>>((const float4*)hdA, coff, deg, col, dinv,
                    bs + 14*16, nullptr, nullptr, (float4*)hPre, NN2);

    pool_kernel<KK2, KK3, 2048><<<BB, 1024>>>((const float4*)hPre, poolw + 32,
                    (float4*)hPool, np, nullptr, 0, nullptr);

    final_kernel<<<BB, 128>>>((const float4*)hPool, linW, linb, out, deg);
}